// round 1
// baseline (speedup 1.0000x reference)
#include <cuda_runtime.h>
#include <math.h>

#define B_MAX 4
#define N_IN 25089      // 1 + 8*56*56
#define T_IN 8
#define H_IN 56
#define W_IN 56
#define HEADS 2
#define QT 8
#define QH 28
#define QW 28
#define QN 6273         // 1 + 8*28*28
#define KT 8
#define KH 7
#define KW 7
#define KN 393          // 1 + 8*7*7
#define ATTN_SCALE 0.102062072615965745f   // 1/sqrt(96)

// ---------------- scratch (device globals; no allocation) ----------------
__device__ float g_q [(size_t)B_MAX * N_IN * 192];   // unpooled q  (b,n,head*96+c)
__device__ float g_k [(size_t)B_MAX * N_IN * 192];   // unpooled k  (sparse: only kv-needed rows valid)
__device__ float g_v [(size_t)B_MAX * N_IN * 192];
__device__ float g_qp[(size_t)B_MAX * 2 * QN * 96];  // pooled+LN q  (bh, n, c)
__device__ float g_kp[(size_t)B_MAX * 2 * KN * 96];
__device__ float g_vp[(size_t)B_MAX * 2 * KN * 96];
__device__ float g_ao[(size_t)B_MAX * QN * 192];     // attention out (b, n, head*96+c)

// Is 1-D coordinate v (in 0..55) touched by the stride-8 kernel-3 pooling windows?
__device__ __forceinline__ bool needed1d(int v) {
    return (v <= 1) || (v >= 7 && v <= 49 && ((v - 7) & 7) <= 2);
}

// ---------------- kernel 1: QKV projection (selective K/V) ----------------
// out(col j of 576) = x . qkv_w[j,:] + qkv_b[j]
//   j <192 -> q ; 192..383 -> k ; 384..575 -> v   (head-major within each)
__global__ void qkv_kernel(const float* __restrict__ x, const float* __restrict__ w,
                           const float* __restrict__ bias, int M)
{
    __shared__ float xs[64][49];
    __shared__ float ws[96][49];
    int tid = threadIdx.x;
    int r0  = blockIdx.x * 64;
    int ty  = tid >> 4;      // 0..15 -> 4 rows each
    int tx  = tid & 15;      // 0..15 -> 6 cols each

    int myNeed = 0;
    if (tid < 64) {
        int r = r0 + tid;
        if (r < M) {
            int n = r % N_IN;
            if (n == 0) myNeed = 1;
            else {
                int tok = n - 1;
                int ww = tok % W_IN;
                int hh = (tok / W_IN) % H_IN;
                myNeed = (needed1d(hh) && needed1d(ww)) ? 1 : 0;
            }
        }
    }
    int any = __syncthreads_or(myNeed);

    for (int cc = 0; cc < 6; ++cc) {
        if (cc >= 2 && !any) continue;   // skip k/v chunks when no pooled window touches
        float acc[4][6];
        #pragma unroll
        for (int i = 0; i < 4; ++i)
            #pragma unroll
            for (int j = 0; j < 6; ++j) acc[i][j] = 0.f;

        for (int kc = 0; kc < 96; kc += 48) {
            __syncthreads();
            for (int l = tid; l < 64 * 48; l += 256) {
                int rr = l / 48, kk = l - rr * 48;
                int r = r0 + rr;
                xs[rr][kk] = (r < M) ? x[(size_t)r * 96 + kc + kk] : 0.f;
            }
            for (int l = tid; l < 96 * 48; l += 256) {
                int cr = l / 48, kk = l - cr * 48;
                ws[cr][kk] = w[(size_t)(cc * 96 + cr) * 96 + kc + kk];
            }
            __syncthreads();
            #pragma unroll 4
            for (int k = 0; k < 48; ++k) {
                float a[4], b[6];
                #pragma unroll
                for (int i = 0; i < 4; ++i) a[i] = xs[ty * 4 + i][k];
                #pragma unroll
                for (int j = 0; j < 6; ++j) b[j] = ws[tx * 6 + j][k];
                #pragma unroll
                for (int i = 0; i < 4; ++i)
                    #pragma unroll
                    for (int j = 0; j < 6; ++j)
                        acc[i][j] = fmaf(a[i], b[j], acc[i][j]);
            }
        }
        #pragma unroll
        for (int i = 0; i < 4; ++i) {
            int r = r0 + ty * 4 + i;
            if (r >= M) continue;
            #pragma unroll
            for (int j = 0; j < 6; ++j) {
                int col = cc * 96 + tx * 6 + j;
                float v = acc[i][j] + bias[col];
                if (col < 192)      g_q[(size_t)r * 192 + col]       = v;
                else if (col < 384) g_k[(size_t)r * 192 + col - 192] = v;
                else                g_v[(size_t)r * 192 + col - 384] = v;
            }
        }
    }
}

// ------------- kernel 2: depthwise conv3d pool + LayerNorm (fused) -------------
// which: 0=q (g_q -> g_qp), 1=k, 2=v.   stride_t is always 1.
__global__ void pool_kernel(const float* __restrict__ cw, const float* __restrict__ gg,
                            const float* __restrict__ bb, int which,
                            int oT, int oH, int oW, int sH, int sW)
{
    int outN = 1 + oT * oH * oW;
    int o    = blockIdx.x;
    int n    = o % outN;
    int head = (o / outN) & 1;
    int b    = o / (outN * 2);
    int c    = threadIdx.x;              // 96 threads

    const float* full = (which == 0) ? g_q : (which == 1) ? g_k : g_v;
    float* outp       = (which == 0) ? g_qp : (which == 1) ? g_kp : g_vp;

    float val;
    if (n == 0) {
        val = full[((size_t)b * N_IN) * 192 + head * 96 + c];
    } else {
        int tn  = n - 1;
        int t2  = tn / (oH * oW);
        int rem = tn % (oH * oW);
        int h2  = rem / oW, w2 = rem % oW;
        float s = 0.f;
        #pragma unroll
        for (int dt = 0; dt < 3; ++dt) {
            int it = t2 + dt - 1;
            if (it < 0 || it >= T_IN) continue;
            #pragma unroll
            for (int dh = 0; dh < 3; ++dh) {
                int ih = h2 * sH + dh - 1;
                if (ih < 0 || ih >= H_IN) continue;
                #pragma unroll
                for (int dw = 0; dw < 3; ++dw) {
                    int iw = w2 * sW + dw - 1;
                    if (iw < 0 || iw >= W_IN) continue;
                    int tok = (it * H_IN + ih) * W_IN + iw;
                    s = fmaf(cw[c * 27 + (dt * 3 + dh) * 3 + dw],
                             full[((size_t)(b * N_IN + 1 + tok)) * 192 + head * 96 + c], s);
                }
            }
        }
        val = s;
    }
    // LayerNorm over the 96 channels
    float s1 = val, s2 = val * val;
    #pragma unroll
    for (int off = 16; off > 0; off >>= 1) {
        s1 += __shfl_xor_sync(0xffffffffu, s1, off);
        s2 += __shfl_xor_sync(0xffffffffu, s2, off);
    }
    __shared__ float p1[3], p2[3], mv[2];
    int wid = c >> 5, lane = c & 31;
    if (lane == 0) { p1[wid] = s1; p2[wid] = s2; }
    __syncthreads();
    if (c == 0) {
        float t1 = p1[0] + p1[1] + p1[2];
        float t2 = p2[0] + p2[1] + p2[2];
        float mean = t1 / 96.f;
        float var  = t2 / 96.f - mean * mean;
        mv[0] = mean;
        mv[1] = rsqrtf(var + 1e-5f);
    }
    __syncthreads();
    float outv = (val - mv[0]) * mv[1] * gg[c] + bb[c];
    outp[((size_t)((b * 2 + head) * outN) + n) * 96 + c] = outv;
}

// ------------- kernel 3: fused attention (scores + relpos + softmax + AV + residual) -------------
__global__ void attn_kernel(const float* __restrict__ rph, const float* __restrict__ rpw,
                            const float* __restrict__ rpt)
{
    __shared__ float qs[16][97];
    __shared__ float sc[16][416];
    __shared__ float ks[32][97];
    __shared__ float srel[16][22];
    __shared__ float rinv[16];

    int tid = threadIdx.x;       // 128 threads
    int bh  = blockIdx.y;
    int q0  = blockIdx.x * 16;
    const float* qp = g_qp + (size_t)bh * QN * 96;
    const float* kp = g_kp + (size_t)bh * KN * 96;
    const float* vp = g_vp + (size_t)bh * KN * 96;

    // zero score pad region (cols >= KN stay 0 so AV needs no guard)
    for (int l = tid; l < 16 * 416; l += 128) (&sc[0][0])[l] = 0.f;

    // load pooled q tile
    for (int l = tid; l < 16 * 96; l += 128) {
        int qi = l / 96, k = l - qi * 96;
        int qr = q0 + qi;
        qs[qi][k] = (qr < QN) ? qp[(size_t)qr * 96 + k] : 0.f;
    }
    __syncthreads();

    // 22 rel-pos dot products per query row: s_t[8], s_h[7], s_w[7]
    for (int idx = tid; idx < 16 * 22; idx += 128) {
        int qi = idx / 22, r = idx - qi * 22;
        int qr = q0 + qi;
        float s = 0.f;
        if (qr > 0 && qr < QN) {
            int tok = qr - 1;
            int tq = tok / (QH * QW);
            int hq = (tok / QW) % QH;
            int wq = tok % QW;
            const float* tab;
            if (r < 8)       tab = rpt + (size_t)(tq - r + 7) * 96;
            else if (r < 15) tab = rph + (size_t)(hq - 4 * (r - 8) + 24) * 96;
            else             tab = rpw + (size_t)(wq - 4 * (r - 15) + 24) * 96;
            #pragma unroll 4
            for (int k = 0; k < 96; ++k) s = fmaf(qs[qi][k], tab[k], s);
        }
        srel[qi][r] = s;
    }

    // QK^T : each thread computes a 2x2 tile of (query, key) dots per chunk
    int qi2 = tid >> 4;   // 0..7
    int jc2 = tid & 15;   // 0..15
    for (int j0 = 0; j0 < KN; j0 += 32) {
        __syncthreads();
        for (int l = tid; l < 32 * 96; l += 128) {
            int jc = l / 96, k = l - jc * 96;
            int j = j0 + jc;
            ks[jc][k] = (j < KN) ? kp[(size_t)j * 96 + k] : 0.f;
        }
        __syncthreads();
        float d00 = 0.f, d01 = 0.f, d10 = 0.f, d11 = 0.f;
        #pragma unroll 4
        for (int k = 0; k < 96; ++k) {
            float a0 = qs[qi2 * 2][k],     a1 = qs[qi2 * 2 + 1][k];
            float b0 = ks[jc2 * 2][k],     b1 = ks[jc2 * 2 + 1][k];
            d00 = fmaf(a0, b0, d00); d01 = fmaf(a0, b1, d01);
            d10 = fmaf(a1, b0, d10); d11 = fmaf(a1, b1, d11);
        }
        int j = j0 + jc2 * 2;
        if (j < KN)     { sc[qi2 * 2][j]     = ATTN_SCALE * d00; sc[qi2 * 2 + 1][j]     = ATTN_SCALE * d10; }
        if (j + 1 < KN) { sc[qi2 * 2][j + 1] = ATTN_SCALE * d01; sc[qi2 * 2 + 1][j + 1] = ATTN_SCALE * d11; }
    }
    __syncthreads();

    // rel-pos add + softmax (8 threads per query row)
    {
        int qi = tid >> 3, s = tid & 7;
        int qr = q0 + qi;
        bool dorel = (qr > 0 && qr < QN);
        float m = -1e30f;
        for (int j = s; j < KN; j += 8) {
            float v = sc[qi][j];
            if (dorel && j >= 1) {
                int kk = j - 1;
                int kt = kk / 49;
                int rm = kk - kt * 49;
                v += srel[qi][kt] + srel[qi][8 + rm / 7] + srel[qi][15 + rm % 7];
            }
            sc[qi][j] = v;
            m = fmaxf(m, v);
        }
        #pragma unroll
        for (int off = 4; off > 0; off >>= 1)
            m = fmaxf(m, __shfl_xor_sync(0xffffffffu, m, off, 8));
        float sum = 0.f;
        for (int j = s; j < KN; j += 8) {
            float e = expf(sc[qi][j] - m);
            sc[qi][j] = e;
            sum += e;
        }
        #pragma unroll
        for (int off = 4; off > 0; off >>= 1)
            sum += __shfl_xor_sync(0xffffffffu, sum, off, 8);
        if (s == 0) rinv[qi] = 1.f / sum;
    }

    // attn @ V : thread owns 2 query rows x 6 channels
    int qig = tid >> 4;            // 0..7
    int c0  = (tid & 15) * 6;      // 16 groups x 6 = 96 channels
    int qiA = qig * 2, qiB = qiA + 1;
    float accA[6] = {0, 0, 0, 0, 0, 0};
    float accB[6] = {0, 0, 0, 0, 0, 0};
    for (int j0 = 0; j0 < KN; j0 += 32) {
        __syncthreads();
        for (int l = tid; l < 32 * 96; l += 128) {
            int jc = l / 96, k = l - jc * 96;
            int j = j0 + jc;
            ks[jc][k] = (j < KN) ? vp[(size_t)j * 96 + k] : 0.f;
        }
        __syncthreads();
        #pragma unroll 4
        for (int jc = 0; jc < 32; ++jc) {
            int j = j0 + jc;
            float pA = sc[qiA][j];
            float pB = sc[qiB][j];
            #pragma unroll
            for (int mI = 0; mI < 6; ++mI) {
                float vv = ks[jc][c0 + mI];
                accA[mI] = fmaf(pA, vv, accA[mI]);
                accB[mI] = fmaf(pB, vv, accB[mI]);
            }
        }
    }
    // normalize + residual (pooled q) + store
    float iA = rinv[qiA], iB = rinv[qiB];
    int b = bh >> 1, head = bh & 1;
    int rA = q0 + qiA, rB = q0 + qiB;
    if (rA < QN) {
        #pragma unroll
        for (int mI = 0; mI < 6; ++mI)
            g_ao[((size_t)(b * QN + rA)) * 192 + head * 96 + c0 + mI] =
                accA[mI] * iA + qs[qiA][c0 + mI];
    }
    if (rB < QN) {
        #pragma unroll
        for (int mI = 0; mI < 6; ++mI)
            g_ao[((size_t)(b * QN + rB)) * 192 + head * 96 + c0 + mI] =
                accB[mI] * iB + qs[qiB][c0 + mI];
    }
}

// ------------- kernel 4: output projection -------------
__global__ void proj_kernel(const float* __restrict__ w, const float* __restrict__ bias,
                            float* __restrict__ out, int M)
{
    __shared__ float xs[64][49];
    __shared__ float ws[96][49];
    int tid = threadIdx.x;
    int r0  = blockIdx.x * 64;
    int ty  = tid >> 4;
    int tx  = tid & 15;

    for (int cc = 0; cc < 2; ++cc) {
        float acc[4][6];
        #pragma unroll
        for (int i = 0; i < 4; ++i)
            #pragma unroll
            for (int j = 0; j < 6; ++j) acc[i][j] = 0.f;

        for (int kc = 0; kc < 192; kc += 48) {
            __syncthreads();
            for (int l = tid; l < 64 * 48; l += 256) {
                int rr = l / 48, kk = l - rr * 48;
                int r = r0 + rr;
                xs[rr][kk] = (r < M) ? g_ao[(size_t)r * 192 + kc + kk] : 0.f;
            }
            for (int l = tid; l < 96 * 48; l += 256) {
                int cr = l / 48, kk = l - cr * 48;
                ws[cr][kk] = w[(size_t)(cc * 96 + cr) * 192 + kc + kk];
            }
            __syncthreads();
            #pragma unroll 4
            for (int k = 0; k < 48; ++k) {
                float a[4], b[6];
                #pragma unroll
                for (int i = 0; i < 4; ++i) a[i] = xs[ty * 4 + i][k];
                #pragma unroll
                for (int j = 0; j < 6; ++j) b[j] = ws[tx * 6 + j][k];
                #pragma unroll
                for (int i = 0; i < 4; ++i)
                    #pragma unroll
                    for (int j = 0; j < 6; ++j)
                        acc[i][j] = fmaf(a[i], b[j], acc[i][j]);
            }
        }
        #pragma unroll
        for (int i = 0; i < 4; ++i) {
            int r = r0 + ty * 4 + i;
            if (r >= M) continue;
            #pragma unroll
            for (int j = 0; j < 6; ++j) {
                int col = cc * 96 + tx * 6 + j;
                out[(size_t)r * 192 + col] = acc[i][j] + bias[col];
            }
        }
    }
}

// ---------------- launch ----------------
extern "C" void kernel_launch(void* const* d_in, const int* in_sizes, int n_in,
                              void* d_out, int out_size)
{
    const float* x      = (const float*)d_in[0];
    const float* qkv_w  = (const float*)d_in[1];
    const float* qkv_b  = (const float*)d_in[2];
    const float* proj_w = (const float*)d_in[3];
    const float* proj_b = (const float*)d_in[4];
    const float* pq_w   = (const float*)d_in[5];
    const float* nq_g   = (const float*)d_in[6];
    const float* nq_b   = (const float*)d_in[7];
    const float* pk_w   = (const float*)d_in[8];
    const float* nk_g   = (const float*)d_in[9];
    const float* nk_b   = (const float*)d_in[10];
    const float* pv_w   = (const float*)d_in[11];
    const float* nv_g   = (const float*)d_in[12];
    const float* nv_b   = (const float*)d_in[13];
    const float* rph    = (const float*)d_in[14];
    const float* rpw    = (const float*)d_in[15];
    const float* rpt    = (const float*)d_in[16];

    int B = in_sizes[0] / (N_IN * 96);
    if (B > B_MAX) B = B_MAX;
    int M = B * N_IN;

    qkv_kernel<<<(M + 63) / 64, 256>>>(x, qkv_w, qkv_b, M);
    pool_kernel<<<B * 2 * QN, 96>>>(pq_w, nq_g, nq_b, 0, QT, QH, QW, 2, 2);
    pool_kernel<<<B * 2 * KN, 96>>>(pk_w, nk_g, nk_b, 1, KT, KH, KW, 8, 8);
    pool_kernel<<<B * 2 * KN, 96>>>(pv_w, nv_g, nv_b, 2, KT, KH, KW, 8, 8);
    attn_kernel<<<dim3((QN + 15) / 16, B * 2), 128>>>(rph, rpw, rpt);
    proj_kernel<<<(B * QN + 63) / 64, 256>>>(proj_w, proj_b, (float*)d_out, B * QN);
}

// round 2
// speedup vs baseline: 1.1430x; 1.1430x over previous
#include <cuda_runtime.h>
#include <math.h>

typedef unsigned long long u64;

#define B_MAX 4
#define N_IN 25089      // 1 + 8*56*56
#define T_IN 8
#define H_IN 56
#define W_IN 56
#define QT 8
#define QH 28
#define QW 28
#define QN 6273         // 1 + 8*28*28
#define KT 8
#define KH 7
#define KW 7
#define KN 393          // 1 + 8*7*7
#define NKV 3201        // 1 + 8*20*20 gathered tokens per batch (KV pooling support)
#define ATTN_SCALE 0.102062072615965745f   // 1/sqrt(96)

// ---------------- scratch (device globals; no allocation) ----------------
__device__ float g_q [(size_t)B_MAX * N_IN * 192];   // unpooled q  (b,n,head*96+c)
__device__ float g_k [(size_t)B_MAX * NKV * 192];    // gathered k  (b,ci,head*96+c)
__device__ float g_v [(size_t)B_MAX * NKV * 192];
__device__ float g_qp[(size_t)B_MAX * 2 * QN * 96];  // pooled+LN q  (bh, n, c)
__device__ float g_kp[(size_t)B_MAX * 2 * KN * 96];
__device__ float g_vp[(size_t)B_MAX * 2 * KN * 96];
__device__ float g_ao[(size_t)B_MAX * QN * 192];     // attention out (b, n, head*96+c)

// ---------------- helpers ----------------
__device__ __forceinline__ void fma2(u64& d, u64 a, u64 b) {
    asm("fma.rn.f32x2 %0, %1, %2, %0;" : "+l"(d) : "l"(a), "l"(b));
}
__device__ __forceinline__ u64 dupf(float v) {
    u64 r; asm("mov.b64 %0, {%1, %1};" : "=l"(r) : "f"(v)); return r;
}
__device__ __forceinline__ float2 u2f(u64 v) {
    float2 r; asm("mov.b64 {%0, %1}, %2;" : "=f"(r.x), "=f"(r.y) : "l"(v)); return r;
}
// gathered-index <-> spatial coordinate maps for the stride-8 / kernel-3 KV pool
__device__ __forceinline__ int hw_from_idx(int i) {
    return (i < 2) ? i : 7 + ((i - 2) / 3) * 8 + ((i - 2) % 3);
}
__device__ __forceinline__ int idx_from_hw(int v) {
    return (v <= 1) ? v : 2 + ((v - 7) >> 3) * 3 + ((v - 7) & 7);
}

// ---------------- kernel 1a: Q projection (all tokens) ----------------
// 128 rows x 96 cols per block, 256 threads, thread = 8 rows x 6 cols, f32x2 packed over row pairs
__global__ void q_proj_kernel(const float* __restrict__ x, const float* __restrict__ w,
                              const float* __restrict__ bias, int M)
{
    __shared__ float xs[32][134];   // k-major, 128 rows (+pad)
    __shared__ float ws2[32][204];  // k-major, 96 cols duplicated as pairs
    int tid = threadIdx.x;
    int r0 = blockIdx.x * 128;
    int cbase = blockIdx.y * 96;
    int ty = tid >> 4, tx = tid & 15;
    int rr0 = ty * 8, cc0 = tx * 6;

    u64 acc[4][6];
    #pragma unroll
    for (int i = 0; i < 4; ++i)
        #pragma unroll
        for (int c = 0; c < 6; ++c) acc[i][c] = 0ull;

    for (int kc = 0; kc < 96; kc += 32) {
        __syncthreads();
        for (int l = tid; l < 128 * 32; l += 256) {
            int row = l >> 5, k = l & 31;
            int r = r0 + row;
            xs[k][row] = (r < M) ? x[(size_t)r * 96 + kc + k] : 0.f;
        }
        for (int l = tid; l < 96 * 32; l += 256) {
            int c = l >> 5, k = l & 31;
            float v = w[(size_t)(cbase + c) * 96 + kc + k];
            ws2[k][2 * c] = v; ws2[k][2 * c + 1] = v;
        }
        __syncthreads();
        #pragma unroll 4
        for (int k = 0; k < 32; ++k) {
            u64 a[4], b[6];
            #pragma unroll
            for (int i = 0; i < 4; ++i) a[i] = *(const u64*)&xs[k][rr0 + 2 * i];
            #pragma unroll
            for (int c = 0; c < 6; ++c) b[c] = *(const u64*)&ws2[k][2 * (cc0 + c)];
            #pragma unroll
            for (int i = 0; i < 4; ++i)
                #pragma unroll
                for (int c = 0; c < 6; ++c) fma2(acc[i][c], a[i], b[c]);
        }
    }
    #pragma unroll
    for (int i = 0; i < 4; ++i) {
        int r = r0 + rr0 + 2 * i;
        #pragma unroll
        for (int c = 0; c < 6; ++c) {
            int col = cbase + cc0 + c;
            float bb = bias[col];
            float2 v = u2f(acc[i][c]);
            if (r < M)     g_q[(size_t)r * 192 + col]       = v.x + bb;
            if (r + 1 < M) g_q[(size_t)(r + 1) * 192 + col] = v.y + bb;
        }
    }
}

// ---------------- kernel 1b: K/V projection (gathered tokens only) ----------------
__global__ void kv_proj_kernel(const float* __restrict__ x, const float* __restrict__ w,
                               const float* __restrict__ bias, int Mkv)
{
    __shared__ float xs[32][134];
    __shared__ float ws2[32][204];
    int tid = threadIdx.x;
    int r0 = blockIdx.x * 128;
    int cbase = blockIdx.y * 96;   // 0,96,192,288 over k|v cols
    int ty = tid >> 4, tx = tid & 15;
    int rr0 = ty * 8, cc0 = tx * 6;

    u64 acc[4][6];
    #pragma unroll
    for (int i = 0; i < 4; ++i)
        #pragma unroll
        for (int c = 0; c < 6; ++c) acc[i][c] = 0ull;

    for (int kc = 0; kc < 96; kc += 32) {
        __syncthreads();
        for (int l = tid; l < 128 * 32; l += 256) {
            int row = l >> 5, k = l & 31;
            int r = r0 + row;
            float v = 0.f;
            if (r < Mkv) {
                int b = r / NKV, ci = r - b * NKV;
                int n = 0;
                if (ci > 0) {
                    int cc = ci - 1;
                    int it = cc / 400, rem = cc - it * 400;
                    int h = hw_from_idx(rem / 20), wv = hw_from_idx(rem % 20);
                    n = 1 + (it * H_IN + h) * W_IN + wv;
                }
                v = x[((size_t)b * N_IN + n) * 96 + kc + k];
            }
            xs[k][row] = v;
        }
        for (int l = tid; l < 96 * 32; l += 256) {
            int c = l >> 5, k = l & 31;
            float v = w[(size_t)(192 + cbase + c) * 96 + kc + k];
            ws2[k][2 * c] = v; ws2[k][2 * c + 1] = v;
        }
        __syncthreads();
        #pragma unroll 4
        for (int k = 0; k < 32; ++k) {
            u64 a[4], b[6];
            #pragma unroll
            for (int i = 0; i < 4; ++i) a[i] = *(const u64*)&xs[k][rr0 + 2 * i];
            #pragma unroll
            for (int c = 0; c < 6; ++c) b[c] = *(const u64*)&ws2[k][2 * (cc0 + c)];
            #pragma unroll
            for (int i = 0; i < 4; ++i)
                #pragma unroll
                for (int c = 0; c < 6; ++c) fma2(acc[i][c], a[i], b[c]);
        }
    }
    #pragma unroll
    for (int i = 0; i < 4; ++i) {
        int r = r0 + rr0 + 2 * i;
        #pragma unroll
        for (int c = 0; c < 6; ++c) {
            int col = cbase + cc0 + c;   // 0..383
            float bb = bias[192 + col];
            float2 v = u2f(acc[i][c]);
            float* dst = (col < 192) ? g_k : g_v;
            int oc = (col < 192) ? col : col - 192;
            if (r < Mkv)     dst[(size_t)r * 192 + oc]       = v.x + bb;
            if (r + 1 < Mkv) dst[(size_t)(r + 1) * 192 + oc] = v.y + bb;
        }
    }
}

// ---------------- kernel 2a: Q pool (stride 1,2,2) + LayerNorm ----------------
__global__ void pool_q_kernel(const float* __restrict__ cw, const float* __restrict__ gg,
                              const float* __restrict__ bb)
{
    int o    = blockIdx.x;
    int n    = o % QN;
    int head = (o / QN) & 1;
    int b    = o / (QN * 2);
    int c    = threadIdx.x;   // 96

    float val;
    if (n == 0) {
        val = g_q[((size_t)b * N_IN) * 192 + head * 96 + c];
    } else {
        int tn  = n - 1;
        int t2  = tn / (QH * QW);
        int rem = tn % (QH * QW);
        int h2  = rem / QW, w2 = rem % QW;
        float s = 0.f;
        #pragma unroll
        for (int dt = 0; dt < 3; ++dt) {
            int it = t2 + dt - 1;
            if (it < 0 || it >= T_IN) continue;
            #pragma unroll
            for (int dh = 0; dh < 3; ++dh) {
                int ih = h2 * 2 + dh - 1;
                if (ih < 0 || ih >= H_IN) continue;
                #pragma unroll
                for (int dw = 0; dw < 3; ++dw) {
                    int iw = w2 * 2 + dw - 1;
                    if (iw < 0 || iw >= W_IN) continue;
                    int tok = (it * H_IN + ih) * W_IN + iw;
                    s = fmaf(cw[c * 27 + (dt * 3 + dh) * 3 + dw],
                             g_q[((size_t)(b * N_IN + 1 + tok)) * 192 + head * 96 + c], s);
                }
            }
        }
        val = s;
    }
    float s1 = val, s2 = val * val;
    #pragma unroll
    for (int off = 16; off > 0; off >>= 1) {
        s1 += __shfl_xor_sync(0xffffffffu, s1, off);
        s2 += __shfl_xor_sync(0xffffffffu, s2, off);
    }
    __shared__ float p1[3], p2[3], mv[2];
    int wid = c >> 5, lane = c & 31;
    if (lane == 0) { p1[wid] = s1; p2[wid] = s2; }
    __syncthreads();
    if (c == 0) {
        float t1 = p1[0] + p1[1] + p1[2];
        float t2 = p2[0] + p2[1] + p2[2];
        float mean = t1 / 96.f;
        float var  = t2 / 96.f - mean * mean;
        mv[0] = mean; mv[1] = rsqrtf(var + 1e-5f);
    }
    __syncthreads();
    g_qp[((size_t)((b * 2 + head) * QN) + n) * 96 + c] = (val - mv[0]) * mv[1] * gg[c] + bb[c];
}

// ---------------- kernel 2b: K/V pool (stride 1,8,8 over gathered tokens) + LN ----------------
__global__ void pool_kv_kernel(const float* __restrict__ cw, const float* __restrict__ gg,
                               const float* __restrict__ bb, int whichV)
{
    int o    = blockIdx.x;
    int n    = o % KN;
    int head = (o / KN) & 1;
    int b    = o / (KN * 2);
    int c    = threadIdx.x;

    const float* src = whichV ? g_v : g_k;
    float* outp      = whichV ? g_vp : g_kp;

    float val;
    if (n == 0) {
        val = src[((size_t)b * NKV) * 192 + head * 96 + c];
    } else {
        int tn  = n - 1;
        int t2  = tn / (KH * KW);
        int rem = tn % (KH * KW);
        int h2  = rem / KW, w2 = rem % KW;
        float s = 0.f;
        #pragma unroll
        for (int dt = 0; dt < 3; ++dt) {
            int it = t2 + dt - 1;
            if (it < 0 || it >= T_IN) continue;
            #pragma unroll
            for (int dh = 0; dh < 3; ++dh) {
                int ih = h2 * 8 + dh - 1;
                if (ih < 0 || ih >= H_IN) continue;
                #pragma unroll
                for (int dw = 0; dw < 3; ++dw) {
                    int iw = w2 * 8 + dw - 1;
                    if (iw < 0 || iw >= W_IN) continue;
                    int ci = 1 + (it * 20 + idx_from_hw(ih)) * 20 + idx_from_hw(iw);
                    s = fmaf(cw[c * 27 + (dt * 3 + dh) * 3 + dw],
                             src[((size_t)(b * NKV + ci)) * 192 + head * 96 + c], s);
                }
            }
        }
        val = s;
    }
    float s1 = val, s2 = val * val;
    #pragma unroll
    for (int off = 16; off > 0; off >>= 1) {
        s1 += __shfl_xor_sync(0xffffffffu, s1, off);
        s2 += __shfl_xor_sync(0xffffffffu, s2, off);
    }
    __shared__ float p1[3], p2[3], mv[2];
    int wid = c >> 5, lane = c & 31;
    if (lane == 0) { p1[wid] = s1; p2[wid] = s2; }
    __syncthreads();
    if (c == 0) {
        float t1 = p1[0] + p1[1] + p1[2];
        float t2 = p2[0] + p2[1] + p2[2];
        float mean = t1 / 96.f;
        float var  = t2 / 96.f - mean * mean;
        mv[0] = mean; mv[1] = rsqrtf(var + 1e-5f);
    }
    __syncthreads();
    outp[((size_t)((b * 2 + head) * KN) + n) * 96 + c] = (val - mv[0]) * mv[1] * gg[c] + bb[c];
}

// ---------------- kernel 3: single-pass fused attention ----------------
// 16 query rows per block, 128 threads, chunks of 64 keys, no-max softmax (scores bounded)
__global__ void attn_kernel(const float* __restrict__ rph, const float* __restrict__ rpw,
                            const float* __restrict__ rpt)
{
    __shared__ float qs_t[96][18];   // q transposed [k][qi]
    __shared__ float kbuf[96 * 68];  // K chunk transposed [k][j] (stride 68) / V chunk [j][c] (stride 98)
    __shared__ float es_t[64][18];   // exp scores transposed [j][qi]
    __shared__ float srel[16][24];   // 22 rel-pos dots per row
    __shared__ float rinv[16];

    int tid = threadIdx.x;   // 128
    int bh  = blockIdx.y;
    int q0  = blockIdx.x * 16;
    const float* qp = g_qp + (size_t)bh * QN * 96;
    const float* kp = g_kp + (size_t)bh * KN * 96;
    const float* vp = g_vp + (size_t)bh * KN * 96;

    for (int l = tid; l < 16 * 96; l += 128) {
        int qi = l / 96, k = l - qi * 96;
        int qr = q0 + qi;
        qs_t[k][qi] = (qr < QN) ? qp[(size_t)qr * 96 + k] : 0.f;
    }
    __syncthreads();

    // rel-pos dot products: s_t[8], s_h[7], s_w[7] per row
    for (int idx = tid; idx < 16 * 22; idx += 128) {
        int qi = idx / 22, r = idx - qi * 22;
        int qr = q0 + qi;
        float s = 0.f;
        if (qr > 0 && qr < QN) {
            int tok = qr - 1;
            int tq = tok / (QH * QW);
            int hq = (tok / QW) % QH;
            int wq = tok % QW;
            const float* tab;
            if (r < 8)       tab = rpt + (size_t)(tq - r + 7) * 96;
            else if (r < 15) tab = rph + (size_t)(hq - 4 * (r - 8) + 24) * 96;
            else             tab = rpw + (size_t)(wq - 4 * (r - 15) + 24) * 96;
            #pragma unroll 4
            for (int k = 0; k < 96; ++k) s = fmaf(qs_t[k][qi], tab[k], s);
        }
        srel[qi][r] = s;
    }

    int qi2 = tid >> 4;       // 0..7 -> rows 2qi2, 2qi2+1
    int jg  = tid & 15;       // score: 4 keys; AV: 6 cols
    int rA  = 2 * qi2;
    int c0  = jg * 6;
    float sumA = 0.f, sumB = 0.f;
    u64 acc[6];
    #pragma unroll
    for (int m = 0; m < 6; ++m) acc[m] = 0ull;

    for (int j0 = 0; j0 < KN; j0 += 64) {
        __syncthreads();
        // load K chunk transposed
        for (int l = tid; l < 64 * 96; l += 128) {
            int jc = l / 96, k = l - jc * 96;
            int j = j0 + jc;
            kbuf[k * 68 + jc] = (j < KN) ? kp[(size_t)j * 96 + k] : 0.f;
        }
        __syncthreads();
        // QK^T: rows packed in f32x2, 4 keys per thread
        u64 d00 = 0ull, d01 = 0ull, d10 = 0ull, d11 = 0ull;
        #pragma unroll 4
        for (int k = 0; k < 96; ++k) {
            float2 aa = *(const float2*)&qs_t[k][rA];
            u64 a0 = dupf(aa.x), a1 = dupf(aa.y);
            float4 bb = *(const float4*)&kbuf[k * 68 + jg * 4];
            u64 b0, b1;
            asm("mov.b64 %0, {%1, %2};" : "=l"(b0) : "f"(bb.x), "f"(bb.y));
            asm("mov.b64 %0, {%1, %2};" : "=l"(b1) : "f"(bb.z), "f"(bb.w));
            fma2(d00, a0, b0); fma2(d01, a0, b1);
            fma2(d10, a1, b0); fma2(d11, a1, b1);
        }
        {
            float2 A0 = u2f(d00), A1 = u2f(d01), B0 = u2f(d10), B1 = u2f(d11);
            float sAv[4] = {A0.x, A0.y, A1.x, A1.y};
            float sBv[4] = {B0.x, B0.y, B1.x, B1.y};
            #pragma unroll
            for (int q = 0; q < 4; ++q) {
                int jc = jg * 4 + q;
                int j = j0 + jc;
                float eA = 0.f, eB = 0.f;
                if (j < KN) {
                    float sA = sAv[q] * ATTN_SCALE, sB = sBv[q] * ATTN_SCALE;
                    if (j > 0) {
                        int kk = j - 1;
                        int kt = kk / 49, rm = kk - kt * 49;
                        int rh = rm / 7,  rw = rm - rh * 7;
                        sA += srel[rA][kt] + srel[rA][8 + rh] + srel[rA][15 + rw];
                        sB += srel[rA + 1][kt] + srel[rA + 1][8 + rh] + srel[rA + 1][15 + rw];
                    }
                    eA = __expf(sA); eB = __expf(sB);
                }
                *(float2*)&es_t[jc][rA] = make_float2(eA, eB);
                sumA += eA; sumB += eB;
            }
        }
        __syncthreads();
        // load V chunk row-major (overwrites K buffer)
        for (int l = tid; l < 64 * 96; l += 128) {
            int jc = l / 96, c = l - jc * 96;
            int j = j0 + jc;
            kbuf[jc * 98 + c] = (j < KN) ? vp[(size_t)j * 96 + c] : 0.f;
        }
        __syncthreads();
        // AV: rows packed f32x2, 6 cols per thread
        #pragma unroll 2
        for (int jc = 0; jc < 64; ++jc) {
            u64 pp = *(const u64*)&es_t[jc][rA];
            const float* vrow = &kbuf[jc * 98 + c0];
            float2 v01 = *(const float2*)&vrow[0];
            float2 v23 = *(const float2*)&vrow[2];
            float2 v45 = *(const float2*)&vrow[4];
            fma2(acc[0], pp, dupf(v01.x));
            fma2(acc[1], pp, dupf(v01.y));
            fma2(acc[2], pp, dupf(v23.x));
            fma2(acc[3], pp, dupf(v23.y));
            fma2(acc[4], pp, dupf(v45.x));
            fma2(acc[5], pp, dupf(v45.y));
        }
    }
    // reduce e-sums across the 16 key-group lanes
    #pragma unroll
    for (int off = 8; off > 0; off >>= 1) {
        sumA += __shfl_xor_sync(0xffffffffu, sumA, off, 16);
        sumB += __shfl_xor_sync(0xffffffffu, sumB, off, 16);
    }
    if (jg == 0) { rinv[rA] = 1.f / sumA; rinv[rA + 1] = 1.f / sumB; }
    __syncthreads();

    float iA = rinv[rA], iB = rinv[rA + 1];
    int b = bh >> 1, head = bh & 1;
    int gA = q0 + rA, gB = gA + 1;
    #pragma unroll
    for (int m = 0; m < 6; ++m) {
        float2 v = u2f(acc[m]);
        if (gA < QN)
            g_ao[((size_t)(b * QN + gA)) * 192 + head * 96 + c0 + m] = v.x * iA + qs_t[c0 + m][rA];
        if (gB < QN)
            g_ao[((size_t)(b * QN + gB)) * 192 + head * 96 + c0 + m] = v.y * iB + qs_t[c0 + m][rA + 1];
    }
}

// ---------------- kernel 4: output projection (K=192) ----------------
__global__ void proj_kernel(const float* __restrict__ w, const float* __restrict__ bias,
                            float* __restrict__ out, int M)
{
    __shared__ float xs[32][134];
    __shared__ float ws2[32][204];
    int tid = threadIdx.x;
    int r0 = blockIdx.x * 128;
    int cbase = blockIdx.y * 96;
    int ty = tid >> 4, tx = tid & 15;
    int rr0 = ty * 8, cc0 = tx * 6;

    u64 acc[4][6];
    #pragma unroll
    for (int i = 0; i < 4; ++i)
        #pragma unroll
        for (int c = 0; c < 6; ++c) acc[i][c] = 0ull;

    for (int kc = 0; kc < 192; kc += 32) {
        __syncthreads();
        for (int l = tid; l < 128 * 32; l += 256) {
            int row = l >> 5, k = l & 31;
            int r = r0 + row;
            xs[k][row] = (r < M) ? g_ao[(size_t)r * 192 + kc + k] : 0.f;
        }
        for (int l = tid; l < 96 * 32; l += 256) {
            int c = l >> 5, k = l & 31;
            float v = w[(size_t)(cbase + c) * 192 + kc + k];
            ws2[k][2 * c] = v; ws2[k][2 * c + 1] = v;
        }
        __syncthreads();
        #pragma unroll 4
        for (int k = 0; k < 32; ++k) {
            u64 a[4], b[6];
            #pragma unroll
            for (int i = 0; i < 4; ++i) a[i] = *(const u64*)&xs[k][rr0 + 2 * i];
            #pragma unroll
            for (int c = 0; c < 6; ++c) b[c] = *(const u64*)&ws2[k][2 * (cc0 + c)];
            #pragma unroll
            for (int i = 0; i < 4; ++i)
                #pragma unroll
                for (int c = 0; c < 6; ++c) fma2(acc[i][c], a[i], b[c]);
        }
    }
    #pragma unroll
    for (int i = 0; i < 4; ++i) {
        int r = r0 + rr0 + 2 * i;
        #pragma unroll
        for (int c = 0; c < 6; ++c) {
            int col = cbase + cc0 + c;
            float bb = bias[col];
            float2 v = u2f(acc[i][c]);
            if (r < M)     out[(size_t)r * 192 + col]       = v.x + bb;
            if (r + 1 < M) out[(size_t)(r + 1) * 192 + col] = v.y + bb;
        }
    }
}

// ---------------- launch ----------------
extern "C" void kernel_launch(void* const* d_in, const int* in_sizes, int n_in,
                              void* d_out, int out_size)
{
    const float* x      = (const float*)d_in[0];
    const float* qkv_w  = (const float*)d_in[1];
    const float* qkv_b  = (const float*)d_in[2];
    const float* proj_w = (const float*)d_in[3];
    const float* proj_b = (const float*)d_in[4];
    const float* pq_w   = (const float*)d_in[5];
    const float* nq_g   = (const float*)d_in[6];
    const float* nq_b   = (const float*)d_in[7];
    const float* pk_w   = (const float*)d_in[8];
    const float* nk_g   = (const float*)d_in[9];
    const float* nk_b   = (const float*)d_in[10];
    const float* pv_w   = (const float*)d_in[11];
    const float* nv_g   = (const float*)d_in[12];
    const float* nv_b   = (const float*)d_in[13];
    const float* rph    = (const float*)d_in[14];
    const float* rpw    = (const float*)d_in[15];
    const float* rpt    = (const float*)d_in[16];

    int B = in_sizes[0] / (N_IN * 96);
    if (B > B_MAX) B = B_MAX;
    int M   = B * N_IN;
    int Mkv = B * NKV;

    q_proj_kernel <<<dim3((M + 127) / 128, 2), 256>>>(x, qkv_w, qkv_b, M);
    kv_proj_kernel<<<dim3((Mkv + 127) / 128, 4), 256>>>(x, qkv_w, qkv_b, Mkv);
    pool_q_kernel <<<B * 2 * QN, 96>>>(pq_w, nq_g, nq_b);
    pool_kv_kernel<<<B * 2 * KN, 96>>>(pk_w, nk_g, nk_b, 0);
    pool_kv_kernel<<<B * 2 * KN, 96>>>(pv_w, nv_g, nv_b, 1);
    attn_kernel   <<<dim3((QN + 15) / 16, B * 2), 128>>>(rph, rpw, rpt);
    proj_kernel   <<<dim3((B * QN + 127) / 128, 2), 256>>>(proj_w, proj_b, (float*)d_out, B * QN);
}

// round 4
// speedup vs baseline: 1.3880x; 1.2144x over previous
#include <cuda_runtime.h>
#include <cuda_bf16.h>
#include <math.h>

typedef unsigned long long u64;
typedef unsigned int u32;

#define B_MAX 4
#define N_IN 25089      // 1 + 8*56*56
#define T_IN 8
#define H_IN 56
#define W_IN 56
#define QT 8
#define QH 28
#define QW 28
#define QN 6273         // 1 + 8*28*28
#define KT 8
#define KH 7
#define KW 7
#define KN 393          // 1 + 8*7*7
#define NKV 3201        // 1 + 8*20*20 gathered tokens per batch
#define ATTN_SCALE 0.102062072615965745f   // 1/sqrt(96)

// ---------------- scratch (device globals; no allocation) ----------------
__device__ float g_q [(size_t)B_MAX * N_IN * 192];
__device__ float g_k [(size_t)B_MAX * NKV * 192];
__device__ float g_v [(size_t)B_MAX * NKV * 192];
__device__ float g_qp[(size_t)B_MAX * 2 * QN * 96];
__device__ float g_kp[(size_t)B_MAX * 2 * KN * 96];
__device__ float g_vp[(size_t)B_MAX * 2 * KN * 96];
__device__ float g_ao[(size_t)B_MAX * QN * 192];

// ---------------- scalar helpers ----------------
__device__ __forceinline__ void fma2(u64& d, u64 a, u64 b) {
    asm("fma.rn.f32x2 %0, %1, %2, %0;" : "+l"(d) : "l"(a), "l"(b));
}
__device__ __forceinline__ u64 dupf(float v) {
    u64 r; asm("mov.b64 %0, {%1, %1};" : "=l"(r) : "f"(v)); return r;
}
__device__ __forceinline__ float2 u2f(u64 v) {
    float2 r; asm("mov.b64 {%0, %1}, %2;" : "=f"(r.x), "=f"(r.y) : "l"(v)); return r;
}
__device__ __forceinline__ int hw_from_idx(int i) {
    return (i < 2) ? i : 7 + ((i - 2) / 3) * 8 + ((i - 2) % 3);
}
__device__ __forceinline__ int idx_from_hw(int v) {
    return (v <= 1) ? v : 2 + ((v - 7) >> 3) * 3 + ((v - 7) & 7);
}
__device__ __forceinline__ u32 smem_u32(const void* p) {
    u32 a;
    asm("{ .reg .u64 t; cvta.to.shared.u64 t, %1; cvt.u32.u64 %0, t; }" : "=r"(a) : "l"(p));
    return a;
}

// ---------------- mma.sync helpers (HMMA path; plain PTX, works on sm_103) ----------------
__device__ __forceinline__ void ldm_x4(u32* r, u32 addr) {
    asm volatile("ldmatrix.sync.aligned.m8n8.x4.shared.b16 {%0,%1,%2,%3}, [%4];"
        : "=r"(r[0]), "=r"(r[1]), "=r"(r[2]), "=r"(r[3]) : "r"(addr));
}
__device__ __forceinline__ void ldm_x2(u32* r, u32 addr) {
    asm volatile("ldmatrix.sync.aligned.m8n8.x2.shared.b16 {%0,%1}, [%2];"
        : "=r"(r[0]), "=r"(r[1]) : "r"(addr));
}
__device__ __forceinline__ void mma_bf16(float* c, const u32* a, const u32* b) {
    asm volatile("mma.sync.aligned.m16n8k16.row.col.f32.bf16.bf16.f32 "
        "{%0,%1,%2,%3}, {%4,%5,%6,%7}, {%8,%9}, {%0,%1,%2,%3};"
        : "+f"(c[0]), "+f"(c[1]), "+f"(c[2]), "+f"(c[3])
        : "r"(a[0]), "r"(a[1]), "r"(a[2]), "r"(a[3]), "r"(b[0]), "r"(b[1]));
}

// ============================================================================
// bf16-split tensor-core GEMM: out[M,192] = in[M,K] @ W[192,K]^T + bias
// io_mode 0: in = x param, out = g_q.  io_mode 1: in = g_ao, out = outp param.
// K must be a multiple of 32.
// ============================================================================
// smem: Ah[128][40] bf16, Al, Bh[192][40], Bl  (stride 40 elems = 80B, conflict-free)
#define GS_AH 0
#define GS_AL 10240
#define GS_BH 20480
#define GS_BL 35840
#define GEMM_SMEM 51200

__global__ void __launch_bounds__(256) gemm192_mma(
    const float* __restrict__ in_x, const float* __restrict__ w,
    const float* __restrict__ bias, float* __restrict__ outp,
    int M, int K, int io_mode)
{
    extern __shared__ char sm[];
    __nv_bfloat16* Ah = (__nv_bfloat16*)(sm + GS_AH);
    __nv_bfloat16* Al = (__nv_bfloat16*)(sm + GS_AL);
    __nv_bfloat16* Bh = (__nv_bfloat16*)(sm + GS_BH);
    __nv_bfloat16* Bl = (__nv_bfloat16*)(sm + GS_BL);
    u32 smb = smem_u32(sm);

    int tid = threadIdx.x;
    int warp = tid >> 5, lane = tid & 31;
    int wm = warp & 3;           // warp row group: 32 rows
    int wn = warp >> 2;          // warp col group: 96 cols
    int rm = wm * 32, cn = wn * 96;
    int r0 = blockIdx.x * 128;

    const float* in = io_mode ? (const float*)g_ao : in_x;
    float* out      = io_mode ? outp : (float*)g_q;

    float C[2][12][4];
    #pragma unroll
    for (int mt = 0; mt < 2; ++mt)
        #pragma unroll
        for (int nt = 0; nt < 12; ++nt)
            #pragma unroll
            for (int i = 0; i < 4; ++i) C[mt][nt][i] = 0.f;

    for (int kc = 0; kc < K; kc += 32) {
        __syncthreads();
        // stage A (hi/lo split), vectorized pairs
        for (int l = tid; l < 128 * 16; l += 256) {
            int row = l >> 4, col = (l & 15) * 2;
            int r = r0 + row;
            float2 v = make_float2(0.f, 0.f);
            if (r < M) v = *(const float2*)&in[(size_t)r * K + kc + col];
            __nv_bfloat162 hi = __floats2bfloat162_rn(v.x, v.y);
            __nv_bfloat162 lo = __floats2bfloat162_rn(v.x - __bfloat162float(hi.x),
                                                      v.y - __bfloat162float(hi.y));
            *(__nv_bfloat162*)(Ah + row * 40 + col) = hi;
            *(__nv_bfloat162*)(Al + row * 40 + col) = lo;
        }
        // stage B (hi/lo split)
        for (int l = tid; l < 192 * 16; l += 256) {
            int row = l >> 4, col = (l & 15) * 2;
            float2 v = *(const float2*)&w[(size_t)row * K + kc + col];
            __nv_bfloat162 hi = __floats2bfloat162_rn(v.x, v.y);
            __nv_bfloat162 lo = __floats2bfloat162_rn(v.x - __bfloat162float(hi.x),
                                                      v.y - __bfloat162float(hi.y));
            *(__nv_bfloat162*)(Bh + row * 40 + col) = hi;
            *(__nv_bfloat162*)(Bl + row * 40 + col) = lo;
        }
        __syncthreads();

        #pragma unroll
        for (int ks = 0; ks < 2; ++ks) {
            int k0 = ks * 16;
            u32 ah[2][4], al[2][4];
            #pragma unroll
            for (int mt = 0; mt < 2; ++mt) {
                u32 off = (u32)(rm + mt * 16 + (lane & 15)) * 80u
                        + (u32)(k0 + ((lane >> 4) << 3)) * 2u;
                ldm_x4(ah[mt], smb + GS_AH + off);
                ldm_x4(al[mt], smb + GS_AL + off);
            }
            #pragma unroll
            for (int nt = 0; nt < 12; ++nt) {
                u32 off = (u32)(cn + nt * 8 + (lane & 7)) * 80u
                        + (u32)(k0 + (((lane >> 3) & 1) << 3)) * 2u;
                u32 bh[2], bl[2];
                ldm_x2(bh, smb + GS_BH + off);
                ldm_x2(bl, smb + GS_BL + off);
                #pragma unroll
                for (int mt = 0; mt < 2; ++mt) {
                    mma_bf16(C[mt][nt], ah[mt], bh);   // hi*hi
                    mma_bf16(C[mt][nt], ah[mt], bl);   // hi*lo
                    mma_bf16(C[mt][nt], al[mt], bh);   // lo*hi
                }
            }
        }
    }

    // epilogue: c0,c1 -> row gr, cols gc,gc+1 ; c2,c3 -> row gr+8
    int gr = lane >> 2;
    int gc = (lane & 3) * 2;
    #pragma unroll
    for (int mt = 0; mt < 2; ++mt) {
        int row0 = r0 + rm + mt * 16 + gr;
        int row1 = row0 + 8;
        #pragma unroll
        for (int nt = 0; nt < 12; ++nt) {
            int col = cn + nt * 8 + gc;
            float b0 = bias[col], b1 = bias[col + 1];
            if (row0 < M) {
                float2 o = make_float2(C[mt][nt][0] + b0, C[mt][nt][1] + b1);
                *(float2*)&out[(size_t)row0 * 192 + col] = o;
            }
            if (row1 < M) {
                float2 o = make_float2(C[mt][nt][2] + b0, C[mt][nt][3] + b1);
                *(float2*)&out[(size_t)row1 * 192 + col] = o;
            }
        }
    }
}

// ---------------- kernel 1b: K/V projection (gathered tokens, fp32) ----------------
__global__ void kv_proj_kernel(const float* __restrict__ x, const float* __restrict__ w,
                               const float* __restrict__ bias, int Mkv)
{
    __shared__ float xs[32][134];
    __shared__ float ws2[32][204];
    int tid = threadIdx.x;
    int r0 = blockIdx.x * 128;
    int cbase = blockIdx.y * 96;
    int ty = tid >> 4, tx = tid & 15;
    int rr0 = ty * 8, cc0 = tx * 6;

    u64 acc[4][6];
    #pragma unroll
    for (int i = 0; i < 4; ++i)
        #pragma unroll
        for (int c = 0; c < 6; ++c) acc[i][c] = 0ull;

    for (int kc = 0; kc < 96; kc += 32) {
        __syncthreads();
        for (int l = tid; l < 128 * 32; l += 256) {
            int row = l >> 5, k = l & 31;
            int r = r0 + row;
            float v = 0.f;
            if (r < Mkv) {
                int b = r / NKV, ci = r - b * NKV;
                int n = 0;
                if (ci > 0) {
                    int cc = ci - 1;
                    int it = cc / 400, rem = cc - it * 400;
                    int h = hw_from_idx(rem / 20), wv = hw_from_idx(rem % 20);
                    n = 1 + (it * H_IN + h) * W_IN + wv;
                }
                v = x[((size_t)b * N_IN + n) * 96 + kc + k];
            }
            xs[k][row] = v;
        }
        for (int l = tid; l < 96 * 32; l += 256) {
            int c = l >> 5, k = l & 31;
            float v = w[(size_t)(192 + cbase + c) * 96 + kc + k];
            ws2[k][2 * c] = v; ws2[k][2 * c + 1] = v;
        }
        __syncthreads();
        #pragma unroll 4
        for (int k = 0; k < 32; ++k) {
            u64 a[4], b[6];
            #pragma unroll
            for (int i = 0; i < 4; ++i) a[i] = *(const u64*)&xs[k][rr0 + 2 * i];
            #pragma unroll
            for (int c = 0; c < 6; ++c) b[c] = *(const u64*)&ws2[k][2 * (cc0 + c)];
            #pragma unroll
            for (int i = 0; i < 4; ++i)
                #pragma unroll
                for (int c = 0; c < 6; ++c) fma2(acc[i][c], a[i], b[c]);
        }
    }
    #pragma unroll
    for (int i = 0; i < 4; ++i) {
        int r = r0 + rr0 + 2 * i;
        #pragma unroll
        for (int c = 0; c < 6; ++c) {
            int col = cbase + cc0 + c;
            float bb = bias[192 + col];
            float2 v = u2f(acc[i][c]);
            float* dst = (col < 192) ? g_k : g_v;
            int oc = (col < 192) ? col : col - 192;
            if (r < Mkv)     dst[(size_t)r * 192 + oc]       = v.x + bb;
            if (r + 1 < Mkv) dst[(size_t)(r + 1) * 192 + oc] = v.y + bb;
        }
    }
}

// ---------------- LN helper (96 threads) ----------------
__device__ __forceinline__ float ln96(float val, const float* gg, const float* bb, int c,
                                      float* p1, float* p2, float* mv)
{
    float s1 = val, s2 = val * val;
    #pragma unroll
    for (int off = 16; off > 0; off >>= 1) {
        s1 += __shfl_xor_sync(0xffffffffu, s1, off);
        s2 += __shfl_xor_sync(0xffffffffu, s2, off);
    }
    int wid = c >> 5, lane = c & 31;
    if (lane == 0) { p1[wid] = s1; p2[wid] = s2; }
    __syncthreads();
    if (c == 0) {
        float t1 = p1[0] + p1[1] + p1[2];
        float t2 = p2[0] + p2[1] + p2[2];
        float mean = t1 / 96.f;
        float var  = t2 / 96.f - mean * mean;
        mv[0] = mean; mv[1] = rsqrtf(var + 1e-5f);
    }
    __syncthreads();
    return (val - mv[0]) * mv[1] * gg[c] + bb[c];
}

// ---------------- kernel 2a: Q pool, patch-shared ----------------
__global__ void pool_q_kernel(const float* __restrict__ cw, const float* __restrict__ gg,
                              const float* __restrict__ bb)
{
    __shared__ float patch[72][96];
    __shared__ float p1[3], p2[3], mv[2];
    int o = blockIdx.x;
    int w2 = o % QW;
    int h2 = (o / QW) % QH;
    int head = (o / (QW * QH)) & 1;
    int b = o / (QW * QH * 2);
    int c = threadIdx.x;

    for (int sp = 0; sp < 72; ++sp) {
        int it = sp / 9, dh = (sp % 9) / 3, dw = sp % 3;
        int ih = 2 * h2 - 1 + dh, iw = 2 * w2 - 1 + dw;
        float v = 0.f;
        if (ih >= 0 && ih < H_IN && iw >= 0 && iw < W_IN) {
            int tok = (it * H_IN + ih) * W_IN + iw;
            v = g_q[((size_t)(b * N_IN + 1 + tok)) * 192 + head * 96 + c];
        }
        patch[sp][c] = v;
    }
    float wreg[27];
    #pragma unroll
    for (int t = 0; t < 27; ++t) wreg[t] = cw[c * 27 + t];
    __syncthreads();

    for (int t2 = 0; t2 < QT; ++t2) {
        float s = 0.f;
        #pragma unroll
        for (int dt = 0; dt < 3; ++dt) {
            int it = t2 + dt - 1;
            if (it < 0 || it >= T_IN) continue;
            #pragma unroll
            for (int dh = 0; dh < 3; ++dh)
                #pragma unroll
                for (int dw = 0; dw < 3; ++dw)
                    s = fmaf(wreg[(dt * 3 + dh) * 3 + dw],
                             patch[it * 9 + dh * 3 + dw][c], s);
        }
        float outv = ln96(s, gg, bb, c, p1, p2, mv);
        int n = 1 + (t2 * QH + h2) * QW + w2;
        g_qp[((size_t)((b * 2 + head) * QN) + n) * 96 + c] = outv;
        __syncthreads();
    }
}

__global__ void cls_q_kernel(const float* __restrict__ gg, const float* __restrict__ bb)
{
    __shared__ float p1[3], p2[3], mv[2];
    int head = blockIdx.x & 1, b = blockIdx.x >> 1;
    int c = threadIdx.x;
    float val = g_q[((size_t)b * N_IN) * 192 + head * 96 + c];
    float outv = ln96(val, gg, bb, c, p1, p2, mv);
    g_qp[((size_t)((b * 2 + head) * QN)) * 96 + c] = outv;
}

// ---------------- kernel 2b: K/V pool + LN ----------------
__global__ void pool_kv_kernel(const float* __restrict__ cw, const float* __restrict__ gg,
                               const float* __restrict__ bb, int whichV)
{
    __shared__ float p1[3], p2[3], mv[2];
    int o    = blockIdx.x;
    int n    = o % KN;
    int head = (o / KN) & 1;
    int b    = o / (KN * 2);
    int c    = threadIdx.x;

    const float* src = whichV ? g_v : g_k;
    float* outp      = whichV ? g_vp : g_kp;

    float val;
    if (n == 0) {
        val = src[((size_t)b * NKV) * 192 + head * 96 + c];
    } else {
        int tn  = n - 1;
        int t2  = tn / (KH * KW);
        int rem = tn % (KH * KW);
        int h2  = rem / KW, w2 = rem % KW;
        float s = 0.f;
        #pragma unroll
        for (int dt = 0; dt < 3; ++dt) {
            int it = t2 + dt - 1;
            if (it < 0 || it >= T_IN) continue;
            #pragma unroll
            for (int dh = 0; dh < 3; ++dh) {
                int ih = h2 * 8 + dh - 1;
                if (ih < 0 || ih >= H_IN) continue;
                #pragma unroll
                for (int dw = 0; dw < 3; ++dw) {
                    int iw = w2 * 8 + dw - 1;
                    if (iw < 0 || iw >= W_IN) continue;
                    int ci = 1 + (it * 20 + idx_from_hw(ih)) * 20 + idx_from_hw(iw);
                    s = fmaf(cw[c * 27 + (dt * 3 + dh) * 3 + dw],
                             src[((size_t)(b * NKV + ci)) * 192 + head * 96 + c], s);
                }
            }
        }
        val = s;
    }
    float outv = ln96(val, gg, bb, c, p1, p2, mv);
    outp[((size_t)((b * 2 + head) * KN) + n) * 96 + c] = outv;
}

// ---------------- kernel 3: fused attention, 32 q-rows / 256 threads ----------------
#define ATTN_SMEM 63488
#define AT_QSD  0                 // [96][66] dup'd q
#define AT_KBUF 6336              // K: [96][68] / V: [64][98]
#define AT_ES   12864             // [64][34] exp scores
#define AT_SREL 15040             // [32][24]
#define AT_RINV 15808             // [32]

__global__ void __launch_bounds__(256) attn_kernel(
    const float* __restrict__ rph, const float* __restrict__ rpw,
    const float* __restrict__ rpt)
{
    extern __shared__ float smf[];
    float* qs_d = smf + AT_QSD;
    float* kbuf = smf + AT_KBUF;
    float* es_t = smf + AT_ES;
    float* srel = smf + AT_SREL;
    float* rinv = smf + AT_RINV;

    int tid = threadIdx.x;   // 256
    int bh  = blockIdx.y;
    int q0  = blockIdx.x * 32;
    const float* qp = g_qp + (size_t)bh * QN * 96;
    const float* kp = g_kp + (size_t)bh * KN * 96;
    const float* vp = g_vp + (size_t)bh * KN * 96;

    for (int l = tid; l < 32 * 96; l += 256) {
        int qi = l / 96, k = l - qi * 96;
        int qr = q0 + qi;
        float v = (qr < QN) ? qp[(size_t)qr * 96 + k] : 0.f;
        qs_d[k * 66 + 2 * qi]     = v;
        qs_d[k * 66 + 2 * qi + 1] = v;
    }
    __syncthreads();

    for (int idx = tid; idx < 32 * 22; idx += 256) {
        int qi = idx / 22, r = idx - qi * 22;
        int qr = q0 + qi;
        float s = 0.f;
        if (qr > 0 && qr < QN) {
            int tok = qr - 1;
            int tq = tok / (QH * QW);
            int hq = (tok / QW) % QH;
            int wq = tok % QW;
            const float* tab;
            if (r < 8)       tab = rpt + (size_t)(tq - r + 7) * 96;
            else if (r < 15) tab = rph + (size_t)(hq - 4 * (r - 8) + 24) * 96;
            else             tab = rpw + (size_t)(wq - 4 * (r - 15) + 24) * 96;
            #pragma unroll 4
            for (int k = 0; k < 96; ++k) s = fmaf(qs_d[k * 66 + 2 * qi], tab[k], s);
        }
        srel[qi * 24 + r] = s;
    }

    int qi2 = tid >> 4;
    int jg  = tid & 15;
    int rA  = 2 * qi2;
    int c0  = jg * 6;
    float sumA = 0.f, sumB = 0.f;
    u64 acc[6];
    #pragma unroll
    for (int m = 0; m < 6; ++m) acc[m] = 0ull;

    for (int j0 = 0; j0 < KN; j0 += 64) {
        __syncthreads();
        for (int l = tid; l < 64 * 96; l += 256) {
            int jc = l / 96, k = l - jc * 96;
            int j = j0 + jc;
            kbuf[k * 68 + jc] = (j < KN) ? kp[(size_t)j * 96 + k] : 0.f;
        }
        __syncthreads();
        u64 d00 = 0ull, d01 = 0ull, d10 = 0ull, d11 = 0ull;
        #pragma unroll 4
        for (int k = 0; k < 96; ++k) {
            u64 a0 = *(const u64*)&qs_d[k * 66 + 2 * rA];
            u64 a1 = *(const u64*)&qs_d[k * 66 + 2 * rA + 2];
            u64 b0 = *(const u64*)&kbuf[k * 68 + jg * 4];
            u64 b1 = *(const u64*)&kbuf[k * 68 + jg * 4 + 2];
            fma2(d00, a0, b0); fma2(d01, a0, b1);
            fma2(d10, a1, b0); fma2(d11, a1, b1);
        }
        {
            float2 A0 = u2f(d00), A1 = u2f(d01), B0 = u2f(d10), B1 = u2f(d11);
            float sAv[4] = {A0.x, A0.y, A1.x, A1.y};
            float sBv[4] = {B0.x, B0.y, B1.x, B1.y};
            #pragma unroll
            for (int q = 0; q < 4; ++q) {
                int jc = jg * 4 + q;
                int j = j0 + jc;
                float eA = 0.f, eB = 0.f;
                if (j < KN) {
                    float sA = sAv[q] * ATTN_SCALE, sB = sBv[q] * ATTN_SCALE;
                    if (j > 0) {
                        int kk = j - 1;
                        int kt = kk / 49, rm = kk - kt * 49;
                        int rh = rm / 7,  rw = rm - rh * 7;
                        sA += srel[rA * 24 + kt] + srel[rA * 24 + 8 + rh] + srel[rA * 24 + 15 + rw];
                        sB += srel[(rA + 1) * 24 + kt] + srel[(rA + 1) * 24 + 8 + rh] + srel[(rA + 1) * 24 + 15 + rw];
                    }
                    eA = __expf(sA); eB = __expf(sB);
                }
                *(float2*)&es_t[jc * 34 + rA] = make_float2(eA, eB);
                sumA += eA; sumB += eB;
            }
        }
        __syncthreads();
        for (int l = tid; l < 64 * 96; l += 256) {
            int jc = l / 96, c = l - jc * 96;
            int j = j0 + jc;
            kbuf[jc * 98 + c] = (j < KN) ? vp[(size_t)j * 96 + c] : 0.f;
        }
        __syncthreads();
        #pragma unroll 2
        for (int jc = 0; jc < 64; ++jc) {
            u64 pp = *(const u64*)&es_t[jc * 34 + rA];
            const float* vrow = &kbuf[jc * 98 + c0];
            float2 v01 = *(const float2*)&vrow[0];
            float2 v23 = *(const float2*)&vrow[2];
            float2 v45 = *(const float2*)&vrow[4];
            fma2(acc[0], pp, dupf(v01.x));
            fma2(acc[1], pp, dupf(v01.y));
            fma2(acc[2], pp, dupf(v23.x));
            fma2(acc[3], pp, dupf(v23.y));
            fma2(acc[4], pp, dupf(v45.x));
            fma2(acc[5], pp, dupf(v45.y));
        }
    }
    #pragma unroll
    for (int off = 8; off > 0; off >>= 1) {
        sumA += __shfl_xor_sync(0xffffffffu, sumA, off, 16);
        sumB += __shfl_xor_sync(0xffffffffu, sumB, off, 16);
    }
    if (jg == 0) { rinv[rA] = 1.f / sumA; rinv[rA + 1] = 1.f / sumB; }
    __syncthreads();

    float iA = rinv[rA], iB = rinv[rA + 1];
    int b = bh >> 1, head = bh & 1;
    int gA = q0 + rA, gB = gA + 1;
    #pragma unroll
    for (int m = 0; m < 6; ++m) {
        float2 v = u2f(acc[m]);
        if (gA < QN)
            g_ao[((size_t)(b * QN + gA)) * 192 + head * 96 + c0 + m] =
                v.x * iA + qs_d[(c0 + m) * 66 + 2 * rA];
        if (gB < QN)
            g_ao[((size_t)(b * QN + gB)) * 192 + head * 96 + c0 + m] =
                v.y * iB + qs_d[(c0 + m) * 66 + 2 * rA + 2];
    }
}

// ---------------- launch ----------------
extern "C" void kernel_launch(void* const* d_in, const int* in_sizes, int n_in,
                              void* d_out, int out_size)
{
    const float* x      = (const float*)d_in[0];
    const float* qkv_w  = (const float*)d_in[1];
    const float* qkv_b  = (const float*)d_in[2];
    const float* proj_w = (const float*)d_in[3];
    const float* proj_b = (const float*)d_in[4];
    const float* pq_w   = (const float*)d_in[5];
    const float* nq_g   = (const float*)d_in[6];
    const float* nq_b   = (const float*)d_in[7];
    const float* pk_w   = (const float*)d_in[8];
    const float* nk_g   = (const float*)d_in[9];
    const float* nk_b   = (const float*)d_in[10];
    const float* pv_w   = (const float*)d_in[11];
    const float* nv_g   = (const float*)d_in[12];
    const float* nv_b   = (const float*)d_in[13];
    const float* rph    = (const float*)d_in[14];
    const float* rpw    = (const float*)d_in[15];
    const float* rpt    = (const float*)d_in[16];

    int B = in_sizes[0] / (N_IN * 96);
    if (B > B_MAX) B = B_MAX;
    int M   = B * N_IN;
    int Mkv = B * NKV;

    cudaFuncSetAttribute(gemm192_mma, cudaFuncAttributeMaxDynamicSharedMemorySize, GEMM_SMEM);
    cudaFuncSetAttribute(attn_kernel, cudaFuncAttributeMaxDynamicSharedMemorySize, ATTN_SMEM);

    gemm192_mma   <<<(M + 127) / 128, 256, GEMM_SMEM>>>(x, qkv_w, qkv_b, nullptr, M, 96, 0);
    kv_proj_kernel<<<dim3((Mkv + 127) / 128, 4), 256>>>(x, qkv_w, qkv_b, Mkv);
    pool_q_kernel <<<B * 2 * QH * QW, 96>>>(pq_w, nq_g, nq_b);
    cls_q_kernel  <<<B * 2, 96>>>(nq_g, nq_b);
    pool_kv_kernel<<<B * 2 * KN, 96>>>(pk_w, nk_g, nk_b, 0);
    pool_kv_kernel<<<B * 2 * KN, 96>>>(pv_w, nv_g, nv_b, 1);
    attn_kernel   <<<dim3((QN + 31) / 32, B * 2), 256, ATTN_SMEM>>>(rph, rpw, rpt);
    gemm192_mma   <<<(B * QN + 127) / 128, 256, GEMM_SMEM>>>(nullptr, proj_w, proj_b,
                                                             (float*)d_out, B * QN, 192, 1);
}